// round 3
// baseline (speedup 1.0000x reference)
#include <cuda_runtime.h>
#include <math.h>

#define NN   20000
#define EE   320000
#define ET   340000      // EE + NN self loops
#define GG   512
#define IND  74
#define EDD  12
#define HIDD 64
#define OUTD 128
#define NH   4
#define F1   256         // NH*HIDD
#define F2   512         // NH*OUTD
#define NEG  0.2f

// ---------------- scratch (static device globals; no allocation) ----------------
static __device__ __align__(16) float g_h1pre[NN * F1];   // x @ W1
static __device__ __align__(16) float g_h1[NN * F1];      // relu(agg1 + b1)
static __device__ __align__(16) float g_h2pre[NN * F2];   // h1 @ W2
static __device__ __align__(16) float g_agg1[NN * F1];
static __device__ __align__(16) float g_agg2[NN * F2];
static __device__ __align__(16) float g_as[NN * NH];
static __device__ __align__(16) float g_ad[NN * NH];
static __device__ __align__(16) float g_ae1[EE * NH];
static __device__ __align__(16) float g_ae2[EE * NH];
static __device__ __align__(16) float g_alpha[ET * NH];
static __device__ unsigned g_mx[NN * NH];
static __device__ float g_sm[NN * NH];
static __device__ float g_meanacc[EDD];
static __device__ float g_V1[EDD * NH];
static __device__ float g_V2[EDD * NH];
static __device__ float g_aeloop1[NH];
static __device__ float g_aeloop2[NH];
static __device__ float g_cnt[GG];
static __device__ float g_emb[GG * OUTD];

// ---------------- helpers ----------------
__device__ __forceinline__ unsigned encf(float f) {
    unsigned u = __float_as_uint(f);
    return (u & 0x80000000u) ? ~u : (u | 0x80000000u);
}
__device__ __forceinline__ float decf(unsigned u) {
    return __uint_as_float((u & 0x80000000u) ? (u & 0x7fffffffu) : ~u);
}
__device__ __forceinline__ void red_add_f4(float4* p, float4 v) {
    asm volatile("red.global.add.v4.f32 [%0], {%1,%2,%3,%4};"
                 :: "l"(p), "f"(v.x), "f"(v.y), "f"(v.z), "f"(v.w) : "memory");
}

// ---------------- init ----------------
__global__ void k_zero_all() {
    int stride = gridDim.x * blockDim.x;
    int i = blockIdx.x * blockDim.x + threadIdx.x;
    for (int j = i; j < NN * F1; j += stride) g_agg1[j] = 0.f;
    for (int j = i; j < NN * F2; j += stride) g_agg2[j] = 0.f;
    for (int j = i; j < GG * OUTD; j += stride) g_emb[j] = 0.f;
    if (i < GG) g_cnt[i] = 0.f;
    if (i < EDD) g_meanacc[i] = 0.f;
}
__global__ void k_init_ms() {
    int i = blockIdx.x * blockDim.x + threadIdx.x;
    if (i < NN * NH) { g_mx[i] = 0u; g_sm[i] = 0.f; }
}

// ---------------- mean of edge_attr ----------------
__global__ void k_mean(const float* __restrict__ ea) {
    __shared__ float s[EDD];
    if (threadIdx.x < EDD) s[threadIdx.x] = 0.f;
    __syncthreads();
    float p[EDD];
#pragma unroll
    for (int d = 0; d < EDD; d++) p[d] = 0.f;
    for (int e = blockIdx.x * blockDim.x + threadIdx.x; e < EE; e += gridDim.x * blockDim.x) {
#pragma unroll
        for (int d = 0; d < EDD; d++) p[d] += ea[e * EDD + d];
    }
#pragma unroll
    for (int d = 0; d < EDD; d++) atomicAdd(&s[d], p[d]);
    __syncthreads();
    if (threadIdx.x < EDD) atomicAdd(&g_meanacc[threadIdx.x], s[threadIdx.x]);
}

// ---------------- tiny precompute: V matrices + self-loop attention terms ----------------
__global__ void k_prep(const float* __restrict__ We1, const float* __restrict__ aev1,
                       const float* __restrict__ We2, const float* __restrict__ aev2) {
    int t = threadIdx.x;  // 64 threads
    if (t < EDD * NH) {
        int d = t / NH, h = t % NH;
        float v1 = 0.f, v2 = 0.f;
        for (int c = 0; c < HIDD; c++) v1 += We1[d * F1 + h * HIDD + c] * aev1[h * HIDD + c];
        for (int c = 0; c < OUTD; c++) v2 += We2[d * F2 + h * OUTD + c] * aev2[h * OUTD + c];
        g_V1[t] = v1; g_V2[t] = v2;
    }
    __syncthreads();
    if (t < NH) {
        float s1 = 0.f, s2 = 0.f;
        for (int d = 0; d < EDD; d++) {
            float m = g_meanacc[d] * (1.f / (float)EE);
            s1 += m * g_V1[d * NH + t];
            s2 += m * g_V2[d * NH + t];
        }
        g_aeloop1[t] = s1; g_aeloop2[t] = s2;
    }
}

// ---------------- SGEMM: picks device-global A/C INSIDE device code ----------------
// LAYER==1: C=g_h1pre[M=NN,K=IND,N=F1], A = x (param)
// LAYER==2: C=g_h2pre[M=NN,K=F1 ,N=F2], A = g_h1 (device global)
template <int LAYER>
__global__ void k_sgemm(const float* __restrict__ A_ext, const float* __restrict__ B) {
    constexpr int K     = (LAYER == 1) ? IND : F1;
    constexpr int Ncols = (LAYER == 1) ? F1  : F2;
    const float* __restrict__ A = (LAYER == 1) ? A_ext : g_h1;
    float* __restrict__ C = (LAYER == 1) ? g_h1pre : g_h2pre;

    __shared__ float As[16][64 + 1];
    __shared__ float Bs[16][64 + 1];
    int tid = threadIdx.x;           // 256 threads
    int trow = tid / 16, tcol = tid % 16;
    int rowBase = blockIdx.y * 64, colBase = blockIdx.x * 64;
    float acc[4][4];
#pragma unroll
    for (int i = 0; i < 4; i++)
#pragma unroll
        for (int j = 0; j < 4; j++) acc[i][j] = 0.f;

    for (int k0 = 0; k0 < K; k0 += 16) {
#pragma unroll
        for (int i = tid; i < 64 * 16; i += 256) {
            int r = i / 16, kk = i % 16;
            int gr = rowBase + r, gk = k0 + kk;
            As[kk][r] = (gr < NN && gk < K) ? A[(size_t)gr * K + gk] : 0.f;
        }
#pragma unroll
        for (int i = tid; i < 16 * 64; i += 256) {
            int kk = i / 64, c = i % 64;
            int gk = k0 + kk, gc = colBase + c;
            Bs[kk][c] = (gk < K && gc < Ncols) ? B[(size_t)gk * Ncols + gc] : 0.f;
        }
        __syncthreads();
#pragma unroll
        for (int kk = 0; kk < 16; kk++) {
            float ar[4], br[4];
#pragma unroll
            for (int i = 0; i < 4; i++) ar[i] = As[kk][trow * 4 + i];
#pragma unroll
            for (int j = 0; j < 4; j++) br[j] = Bs[kk][tcol * 4 + j];
#pragma unroll
            for (int i = 0; i < 4; i++)
#pragma unroll
                for (int j = 0; j < 4; j++) acc[i][j] += ar[i] * br[j];
        }
        __syncthreads();
    }
#pragma unroll
    for (int i = 0; i < 4; i++) {
        int r = rowBase + trow * 4 + i;
        if (r >= NN) continue;
#pragma unroll
        for (int j = 0; j < 4; j++) {
            int c = colBase + tcol * 4 + j;
            if (c < Ncols) C[(size_t)r * Ncols + c] = acc[i][j];
        }
    }
}

// ---------------- per-node attention dots: as[n,h], ad[n,h] ----------------
template <int LAYER>
__global__ void k_asad(const float* __restrict__ a_s, const float* __restrict__ a_d) {
    constexpr int C = (LAYER == 1) ? HIDD : OUTD;
    const float* __restrict__ h = (LAYER == 1) ? g_h1pre : g_h2pre;
    int warp = (blockIdx.x * blockDim.x + threadIdx.x) >> 5;
    int lane = threadIdx.x & 31;
    if (warp >= NN * NH) return;
    int n = warp / NH, hh = warp % NH;
    const float* row = h + (size_t)n * (NH * C) + hh * C;
    const float* vs = a_s + hh * C;
    const float* vd = a_d + hh * C;
    float s = 0.f, d = 0.f;
    for (int c = lane; c < C; c += 32) {
        float v = row[c];
        s += v * vs[c];
        d += v * vd[c];
    }
#pragma unroll
    for (int o = 16; o; o >>= 1) {
        s += __shfl_down_sync(0xffffffffu, s, o);
        d += __shfl_down_sync(0xffffffffu, d, o);
    }
    if (lane == 0) { g_as[warp] = s; g_ad[warp] = d; }
}

// ---------------- per-edge attention terms (both layers in one pass) ----------------
__global__ void k_edge_ae(const float* __restrict__ ea) {
    int e = blockIdx.x * blockDim.x + threadIdx.x;
    if (e >= EE) return;
    float a1[NH] = {0.f, 0.f, 0.f, 0.f};
    float a2[NH] = {0.f, 0.f, 0.f, 0.f};
#pragma unroll
    for (int d = 0; d < EDD; d++) {
        float v = ea[e * EDD + d];
#pragma unroll
        for (int h = 0; h < NH; h++) {
            a1[h] += v * g_V1[d * NH + h];
            a2[h] += v * g_V2[d * NH + h];
        }
    }
#pragma unroll
    for (int h = 0; h < NH; h++) {
        g_ae1[e * NH + h] = a1[h];
        g_ae2[e * NH + h] = a2[h];
    }
}

// ---------------- alpha = lrelu(as[src]+ad[dst]+ae), segment max ----------------
__global__ void k_alpha_max(const int* __restrict__ src, const int* __restrict__ dst, int layer) {
    int e = blockIdx.x * blockDim.x + threadIdx.x;
    if (e >= ET) return;
    const float* ae = (layer == 1) ? g_ae1 : g_ae2;
    const float* aeloop = (layer == 1) ? g_aeloop1 : g_aeloop2;
    int s, d;
    float av[NH];
    if (e < EE) {
        s = src[e]; d = dst[e];
#pragma unroll
        for (int h = 0; h < NH; h++) av[h] = ae[e * NH + h];
    } else {
        s = d = e - EE;
#pragma unroll
        for (int h = 0; h < NH; h++) av[h] = aeloop[h];
    }
#pragma unroll
    for (int h = 0; h < NH; h++) {
        float a = g_as[s * NH + h] + g_ad[d * NH + h] + av[h];
        a = (a >= 0.f) ? a : NEG * a;
        g_alpha[e * NH + h] = a;
        atomicMax(&g_mx[d * NH + h], encf(a));
    }
}

// ---------------- ex = exp(alpha - max), segment sum ----------------
__global__ void k_exp_sum(const int* __restrict__ dst) {
    int e = blockIdx.x * blockDim.x + threadIdx.x;
    if (e >= ET) return;
    int d = (e < EE) ? dst[e] : (e - EE);
#pragma unroll
    for (int h = 0; h < NH; h++) {
        float m = decf(g_mx[d * NH + h]);
        float x = __expf(g_alpha[e * NH + h] - m);
        g_alpha[e * NH + h] = x;
        atomicAdd(&g_sm[d * NH + h], x);
    }
}

// ---------------- weighted scatter-aggregate ----------------
template <int F>
__global__ void k_agg(const int* __restrict__ src, const int* __restrict__ dst) {
    constexpr int TPE = F / 4;       // threads per edge (float4 each)
    constexpr int CH = F / NH;       // feats per head
    const float* __restrict__ h = (F == F1) ? g_h1pre : g_h2pre;
    float* __restrict__ agg = (F == F1) ? g_agg1 : g_agg2;
    int t = blockIdx.x * blockDim.x + threadIdx.x;
    int e = t / TPE, lane = t % TPE;
    if (e >= ET) return;
    int s, d;
    if (e < EE) { s = src[e]; d = dst[e]; } else { s = d = e - EE; }
    int hh = (lane * 4) / CH;
    float w = g_alpha[e * NH + hh] / (g_sm[d * NH + hh] + 1e-16f);
    float4 v = reinterpret_cast<const float4*>(h + (size_t)s * F)[lane];
    v.x *= w; v.y *= w; v.z *= w; v.w *= w;
    red_add_f4(reinterpret_cast<float4*>(agg + (size_t)d * F) + lane, v);
}

// ---------------- epilogues ----------------
__global__ void k_fin1(const float* __restrict__ b1) {
    int i = blockIdx.x * blockDim.x + threadIdx.x;
    if (i >= NN * F1) return;
    float v = g_agg1[i] + b1[i % F1];
    g_h1[i] = v > 0.f ? v : 0.f;
}
__global__ void k_fin2(const float* __restrict__ b2, float* __restrict__ out) {
    int i = blockIdx.x * blockDim.x + threadIdx.x;
    if (i >= NN * OUTD) return;
    int n = i / OUTD, c = i % OUTD;
    const float* a = g_agg2 + (size_t)n * F2;
    float v = 0.25f * (a[c] + a[OUTD + c] + a[2 * OUTD + c] + a[3 * OUTD + c]) + b2[c];
    out[i] = v > 0.f ? v : 0.f;
}

// ---------------- pooling ----------------
__global__ void k_cnt(const int* __restrict__ batch) {
    int n = blockIdx.x * blockDim.x + threadIdx.x;
    if (n < NN) atomicAdd(&g_cnt[batch[n]], 1.f);
}
__global__ void k_pool(const int* __restrict__ batch, const float* __restrict__ h2) {
    int i = blockIdx.x * blockDim.x + threadIdx.x;
    if (i >= NN * OUTD) return;
    int n = i / OUTD, c = i % OUTD;
    atomicAdd(&g_emb[batch[n] * OUTD + c], h2[i]);
}
__global__ void k_pool_div(float* __restrict__ out_emb) {
    int i = blockIdx.x * blockDim.x + threadIdx.x;
    if (i >= GG * OUTD) return;
    int g = i / OUTD;
    out_emb[i] = g_emb[i] / fmaxf(g_cnt[g], 1.f);
}

// ---------------- launcher ----------------
extern "C" void kernel_launch(void* const* d_in, const int* in_sizes, int n_in,
                              void* d_out, int out_size) {
    const float* x      = (const float*)d_in[0];
    const float* ea     = (const float*)d_in[1];
    const float* W1     = (const float*)d_in[2];
    const float* a_src1 = (const float*)d_in[3];
    const float* a_dst1 = (const float*)d_in[4];
    const float* We1    = (const float*)d_in[5];
    const float* a_e1   = (const float*)d_in[6];
    const float* b1     = (const float*)d_in[7];
    const float* W2     = (const float*)d_in[8];
    const float* a_src2 = (const float*)d_in[9];
    const float* a_dst2 = (const float*)d_in[10];
    const float* We2    = (const float*)d_in[11];
    const float* a_e2   = (const float*)d_in[12];
    const float* b2     = (const float*)d_in[13];
    const int* ei       = (const int*)d_in[14];
    const int* batch    = (const int*)d_in[15];
    const int* srcp = ei;
    const int* dstp = ei + EE;
    float* out = (float*)d_out;          // [NN*OUTD] h2, then [GG*OUTD] graph_emb
    float* out_emb = out + (size_t)NN * OUTD;

    k_zero_all<<<2048, 256>>>();
    k_mean<<<256, 256>>>(ea);
    k_prep<<<1, 64>>>(We1, a_e1, We2, a_e2);

    // ---- layer 1 ----
    {
        dim3 g(F1 / 64, (NN + 63) / 64);
        k_sgemm<1><<<g, 256>>>(x, W1);
    }
    k_asad<1><<<(NN * NH * 32 + 255) / 256, 256>>>(a_src1, a_dst1);
    k_edge_ae<<<(EE + 255) / 256, 256>>>(ea);
    k_init_ms<<<(NN * NH + 255) / 256, 256>>>();
    k_alpha_max<<<(ET + 255) / 256, 256>>>(srcp, dstp, 1);
    k_exp_sum<<<(ET + 255) / 256, 256>>>(dstp);
    k_agg<F1><<<(ET * (F1 / 4) + 255) / 256, 256>>>(srcp, dstp);
    k_fin1<<<(NN * F1 + 255) / 256, 256>>>(b1);

    // ---- layer 2 ----
    {
        dim3 g(F2 / 64, (NN + 63) / 64);
        k_sgemm<2><<<g, 256>>>(nullptr, W2);
    }
    k_asad<2><<<(NN * NH * 32 + 255) / 256, 256>>>(a_src2, a_dst2);
    k_init_ms<<<(NN * NH + 255) / 256, 256>>>();
    k_alpha_max<<<(ET + 255) / 256, 256>>>(srcp, dstp, 2);
    k_exp_sum<<<(ET + 255) / 256, 256>>>(dstp);
    k_agg<F2><<<(ET * (F2 / 4) + 255) / 256, 256>>>(srcp, dstp);
    k_fin2<<<(NN * OUTD + 255) / 256, 256>>>(b2, out);

    // ---- pooling ----
    k_cnt<<<(NN + 255) / 256, 256>>>(batch);
    k_pool<<<(NN * OUTD + 255) / 256, 256>>>(batch, out);
    if (out_size >= NN * OUTD + GG * OUTD)
        k_pool_div<<<(GG * OUTD + 255) / 256, 256>>>(out_emb);
}

// round 5
// speedup vs baseline: 1.5257x; 1.5257x over previous
#include <cuda_runtime.h>
#include <math.h>

#define NN   20000
#define EE   320000
#define ET   340000      // EE + NN self loops
#define GG   512
#define IND  74
#define EDD  12
#define HIDD 64
#define OUTD 128
#define NH   4
#define F1   256         // NH*HIDD
#define F2   512         // NH*OUTD
#define NEG  0.2f

// ---------------- scratch (static device globals; no allocation) ----------------
static __device__ __align__(16) float g_h1pre[NN * F1];   // x @ W1
static __device__ __align__(16) float g_h1[NN * F1];      // layer-1 output
static __device__ __align__(16) float g_h2pre[NN * F2];   // h1 @ W2
static __device__ __align__(16) float g_as[NN * NH];
static __device__ __align__(16) float g_ad[NN * NH];
static __device__ __align__(16) float g_ae1[EE * NH];
static __device__ __align__(16) float g_ae2[EE * NH];
static __device__ float g_meanacc[EDD];
static __device__ float g_V1[EDD * NH];
static __device__ float g_V2[EDD * NH];
static __device__ float g_aeloop1[NH];
static __device__ float g_aeloop2[NH];
static __device__ float g_cnt[GG];
static __device__ float g_emb[GG * OUTD];
// CSR by destination
static __device__ int g_deg[NN];
static __device__ int g_off[NN + 1];
static __device__ int g_cur[NN];
static __device__ int g_csr_src[ET];
static __device__ int g_csr_eid[ET];   // -1 => self loop

// ---------------- init ----------------
__global__ void k_zero_all() {
    int stride = gridDim.x * blockDim.x;
    int i = blockIdx.x * blockDim.x + threadIdx.x;
    for (int j = i; j < GG * OUTD; j += stride) g_emb[j] = 0.f;
    for (int j = i; j < NN; j += stride) g_deg[j] = 1;   // self loop
    if (i < GG) g_cnt[i] = 0.f;
    if (i < EDD) g_meanacc[i] = 0.f;
}

// ---------------- mean of edge_attr ----------------
__global__ void k_mean(const float* __restrict__ ea) {
    __shared__ float s[EDD];
    if (threadIdx.x < EDD) s[threadIdx.x] = 0.f;
    __syncthreads();
    float p[EDD];
#pragma unroll
    for (int d = 0; d < EDD; d++) p[d] = 0.f;
    for (int e = blockIdx.x * blockDim.x + threadIdx.x; e < EE; e += gridDim.x * blockDim.x) {
#pragma unroll
        for (int d = 0; d < EDD; d++) p[d] += ea[e * EDD + d];
    }
#pragma unroll
    for (int d = 0; d < EDD; d++) atomicAdd(&s[d], p[d]);
    __syncthreads();
    if (threadIdx.x < EDD) atomicAdd(&g_meanacc[threadIdx.x], s[threadIdx.x]);
}

// ---------------- tiny precompute: V matrices + self-loop attention terms ----------------
__global__ void k_prep(const float* __restrict__ We1, const float* __restrict__ aev1,
                       const float* __restrict__ We2, const float* __restrict__ aev2) {
    int t = threadIdx.x;  // 64 threads
    if (t < EDD * NH) {
        int d = t / NH, h = t % NH;
        float v1 = 0.f, v2 = 0.f;
        for (int c = 0; c < HIDD; c++) v1 += We1[d * F1 + h * HIDD + c] * aev1[h * HIDD + c];
        for (int c = 0; c < OUTD; c++) v2 += We2[d * F2 + h * OUTD + c] * aev2[h * OUTD + c];
        g_V1[t] = v1; g_V2[t] = v2;
    }
    __syncthreads();
    if (t < NH) {
        float s1 = 0.f, s2 = 0.f;
        for (int d = 0; d < EDD; d++) {
            float m = g_meanacc[d] * (1.f / (float)EE);
            s1 += m * g_V1[d * NH + t];
            s2 += m * g_V2[d * NH + t];
        }
        g_aeloop1[t] = s1; g_aeloop2[t] = s2;
    }
}

// ---------------- CSR build ----------------
__global__ void k_deg(const int* __restrict__ dst) {
    int e = blockIdx.x * blockDim.x + threadIdx.x;
    if (e < EE) atomicAdd(&g_deg[dst[e]], 1);
}
__global__ void k_scan() {   // single block, 1024 threads
    __shared__ int partial[1024];
    const int CHW = (NN + 1023) / 1024;
    int t = threadIdx.x;
    int base = t * CHW;
    int sum = 0;
    for (int i = 0; i < CHW; i++) {
        int idx = base + i;
        if (idx < NN) sum += g_deg[idx];
    }
    partial[t] = sum;
    __syncthreads();
    for (int ofs = 1; ofs < 1024; ofs <<= 1) {
        int v = 0;
        if (t >= ofs) v = partial[t - ofs];
        __syncthreads();
        if (t >= ofs) partial[t] += v;
        __syncthreads();
    }
    int run = (t == 0) ? 0 : partial[t - 1];
    for (int i = 0; i < CHW; i++) {
        int idx = base + i;
        if (idx < NN) { g_off[idx] = run; run += g_deg[idx]; }
    }
    if (t == 1023) g_off[NN] = partial[1023];
}
__global__ void k_fill_self() {
    int n = blockIdx.x * blockDim.x + threadIdx.x;
    if (n >= NN) return;
    int o = g_off[n];
    g_csr_src[o] = n;
    g_csr_eid[o] = -1;
    g_cur[n] = o + 1;
}
__global__ void k_fill_edges(const int* __restrict__ src, const int* __restrict__ dst) {
    int e = blockIdx.x * blockDim.x + threadIdx.x;
    if (e >= EE) return;
    int p = atomicAdd(&g_cur[dst[e]], 1);
    g_csr_src[p] = src[e];
    g_csr_eid[p] = e;
}

// ---------------- SGEMM 128x128x8, 8x8 microtile, double buffered ----------------
template <int LAYER>
__global__ void __launch_bounds__(256) k_sgemm(const float* __restrict__ A_ext,
                                               const float* __restrict__ B) {
    constexpr int K  = (LAYER == 1) ? IND : F1;
    constexpr int NC = (LAYER == 1) ? F1  : F2;
    const float* __restrict__ A = (LAYER == 1) ? A_ext : g_h1;
    float* __restrict__ C = (LAYER == 1) ? g_h1pre : g_h2pre;
    constexpr int BM = 128, BN = 128, BK = 8;

    __shared__ float As[2][BK][BM];
    __shared__ float Bs[2][BK][BN];
    int tid = threadIdx.x;
    int row0 = blockIdx.y * BM, col0 = blockIdx.x * BN;
    int tx = tid % 16, ty = tid / 16;
    int ar = tid >> 1, ak = (tid & 1) * 4;       // A load: row, k-quad
    int bk = tid >> 5, bn = (tid & 31) * 4;      // B load: k, col-quad

    float acc[8][8];
#pragma unroll
    for (int i = 0; i < 8; i++)
#pragma unroll
        for (int j = 0; j < 8; j++) acc[i][j] = 0.f;

    auto loadA = [&](int stage, int k0) {
        int grow = row0 + ar;
        float v[4];
#pragma unroll
        for (int i = 0; i < 4; i++) {
            int gk = k0 + ak + i;
            v[i] = (grow < NN && gk < K) ? A[(size_t)grow * K + gk] : 0.f;
        }
#pragma unroll
        for (int i = 0; i < 4; i++) As[stage][ak + i][ar] = v[i];
    };
    auto loadB = [&](int stage, int k0) {
        int gk = k0 + bk;
        float4 v = make_float4(0.f, 0.f, 0.f, 0.f);
        if (gk < K) v = *reinterpret_cast<const float4*>(&B[(size_t)gk * NC + col0 + bn]);
        *reinterpret_cast<float4*>(&Bs[stage][bk][bn]) = v;
    };

    loadA(0, 0); loadB(0, 0);
    __syncthreads();
    constexpr int NK = (K + BK - 1) / BK;
    for (int kt = 0; kt < NK; kt++) {
        int cur = kt & 1, nxt = cur ^ 1;
        if (kt + 1 < NK) { loadA(nxt, (kt + 1) * BK); loadB(nxt, (kt + 1) * BK); }
        float ra[8], rb[8];
#pragma unroll
        for (int kk = 0; kk < BK; kk++) {
#pragma unroll
            for (int i = 0; i < 8; i++) ra[i] = As[cur][kk][ty * 8 + i];
#pragma unroll
            for (int j = 0; j < 8; j++) rb[j] = Bs[cur][kk][tx * 8 + j];
#pragma unroll
            for (int i = 0; i < 8; i++)
#pragma unroll
                for (int j = 0; j < 8; j++) acc[i][j] += ra[i] * rb[j];
        }
        __syncthreads();
    }
#pragma unroll
    for (int i = 0; i < 8; i++) {
        int r = row0 + ty * 8 + i;
        if (r >= NN) continue;
#pragma unroll
        for (int j = 0; j < 8; j += 4) {
            int c = col0 + tx * 8 + j;
            float4 v = make_float4(acc[i][j], acc[i][j + 1], acc[i][j + 2], acc[i][j + 3]);
            *reinterpret_cast<float4*>(&C[(size_t)r * NC + c]) = v;
        }
    }
}

// ---------------- per-node attention dots: as[n,h], ad[n,h] ----------------
template <int LAYER>
__global__ void k_asad(const float* __restrict__ a_s, const float* __restrict__ a_d) {
    constexpr int C = (LAYER == 1) ? HIDD : OUTD;
    const float* __restrict__ h = (LAYER == 1) ? g_h1pre : g_h2pre;
    int warp = (blockIdx.x * blockDim.x + threadIdx.x) >> 5;
    int lane = threadIdx.x & 31;
    if (warp >= NN * NH) return;
    int n = warp / NH, hh = warp % NH;
    const float* row = h + (size_t)n * (NH * C) + hh * C;
    const float* vs = a_s + hh * C;
    const float* vd = a_d + hh * C;
    float s = 0.f, d = 0.f;
    for (int c = lane; c < C; c += 32) {
        float v = row[c];
        s += v * vs[c];
        d += v * vd[c];
    }
#pragma unroll
    for (int o = 16; o; o >>= 1) {
        s += __shfl_down_sync(0xffffffffu, s, o);
        d += __shfl_down_sync(0xffffffffu, d, o);
    }
    if (lane == 0) { g_as[warp] = s; g_ad[warp] = d; }
}

// ---------------- per-edge attention terms (both layers in one pass) ----------------
__global__ void k_edge_ae(const float* __restrict__ ea) {
    int e = blockIdx.x * blockDim.x + threadIdx.x;
    if (e >= EE) return;
    float a1[NH] = {0.f, 0.f, 0.f, 0.f};
    float a2[NH] = {0.f, 0.f, 0.f, 0.f};
#pragma unroll
    for (int d = 0; d < EDD; d++) {
        float v = ea[e * EDD + d];
#pragma unroll
        for (int h = 0; h < NH; h++) {
            a1[h] += v * g_V1[d * NH + h];
            a2[h] += v * g_V2[d * NH + h];
        }
    }
#pragma unroll
    for (int h = 0; h < NH; h++) {
        g_ae1[e * NH + h] = a1[h];
        g_ae2[e * NH + h] = a2[h];
    }
}

// ---------------- fused attention softmax + aggregate (one block per dst node) ----------------
// pass1: streaming max over incoming edges; pass2: acc += exp(a-max)*h[src], s += exp;
// write acc/s with epilogue (L1: +bias, relu -> g_h1; L2: head mean, +bias, relu -> out, pool).
template <int LAYER>
__global__ void k_attn_agg(const float* __restrict__ bias, const int* __restrict__ batch,
                           float* __restrict__ out) {
    constexpr int F  = (LAYER == 1) ? F1 : F2;
    constexpr int CH = F / NH;
    constexpr int T  = F / 4;            // threads per block
    const float* __restrict__ ae = (LAYER == 1) ? g_ae1 : g_ae2;
    const float* __restrict__ aeloop = (LAYER == 1) ? g_aeloop1 : g_aeloop2;
    const float4* __restrict__ hp =
        reinterpret_cast<const float4*>((LAYER == 1) ? g_h1pre : g_h2pre);

    int n = blockIdx.x;
    int t = threadIdx.x;
    int h = (t * 4) / CH;
    int begin = g_off[n], end = g_off[n + 1];
    float ad_n = g_ad[n * NH + h];

    // pass 1: max
    float mx = -INFINITY;
    for (int i = begin; i < end; i++) {
        int s = __ldg(&g_csr_src[i]);
        int eid = __ldg(&g_csr_eid[i]);
        float av = (eid >= 0) ? __ldg(&ae[eid * NH + h]) : aeloop[h];
        float a = __ldg(&g_as[s * NH + h]) + ad_n + av;
        a = (a >= 0.f) ? a : NEG * a;
        mx = fmaxf(mx, a);
    }
    // pass 2: accumulate
    float4 acc = make_float4(0.f, 0.f, 0.f, 0.f);
    float ssum = 0.f;
    for (int i = begin; i < end; i++) {
        int s = __ldg(&g_csr_src[i]);
        int eid = __ldg(&g_csr_eid[i]);
        float av = (eid >= 0) ? __ldg(&ae[eid * NH + h]) : aeloop[h];
        float a = __ldg(&g_as[s * NH + h]) + ad_n + av;
        a = (a >= 0.f) ? a : NEG * a;
        float ex = __expf(a - mx);
        ssum += ex;
        float4 v = hp[(size_t)s * T + t];
        acc.x += ex * v.x; acc.y += ex * v.y; acc.z += ex * v.z; acc.w += ex * v.w;
    }
    float inv = 1.f / (ssum + 1e-16f);
    acc.x *= inv; acc.y *= inv; acc.z *= inv; acc.w *= inv;

    if (LAYER == 1) {
        float4 b = *reinterpret_cast<const float4*>(&bias[t * 4]);
        float4 r;
        r.x = fmaxf(acc.x + b.x, 0.f);
        r.y = fmaxf(acc.y + b.y, 0.f);
        r.z = fmaxf(acc.z + b.z, 0.f);
        r.w = fmaxf(acc.w + b.w, 0.f);
        reinterpret_cast<float4*>(g_h1)[(size_t)n * T + t] = r;
    } else {
        __shared__ float sbuf[F2];
        *reinterpret_cast<float4*>(&sbuf[t * 4]) = acc;
        __syncthreads();
        // t in [0,128): output feature c = t
        int c = t;
        float v = 0.25f * (sbuf[c] + sbuf[OUTD + c] + sbuf[2 * OUTD + c] + sbuf[3 * OUTD + c])
                  + bias[c];
        v = fmaxf(v, 0.f);
        out[(size_t)n * OUTD + c] = v;
        atomicAdd(&g_emb[batch[n] * OUTD + c], v);
    }
}

// ---------------- pooling tail ----------------
__global__ void k_cnt(const int* __restrict__ batch) {
    int n = blockIdx.x * blockDim.x + threadIdx.x;
    if (n < NN) atomicAdd(&g_cnt[batch[n]], 1.f);
}
__global__ void k_pool_div(float* __restrict__ out_emb) {
    int i = blockIdx.x * blockDim.x + threadIdx.x;
    if (i >= GG * OUTD) return;
    int g = i / OUTD;
    out_emb[i] = g_emb[i] / fmaxf(g_cnt[g], 1.f);
}

// ---------------- launcher ----------------
extern "C" void kernel_launch(void* const* d_in, const int* in_sizes, int n_in,
                              void* d_out, int out_size) {
    const float* x      = (const float*)d_in[0];
    const float* ea     = (const float*)d_in[1];
    const float* W1     = (const float*)d_in[2];
    const float* a_src1 = (const float*)d_in[3];
    const float* a_dst1 = (const float*)d_in[4];
    const float* We1    = (const float*)d_in[5];
    const float* a_e1   = (const float*)d_in[6];
    const float* b1     = (const float*)d_in[7];
    const float* W2     = (const float*)d_in[8];
    const float* a_src2 = (const float*)d_in[9];
    const float* a_dst2 = (const float*)d_in[10];
    const float* We2    = (const float*)d_in[11];
    const float* a_e2   = (const float*)d_in[12];
    const float* b2     = (const float*)d_in[13];
    const int* ei       = (const int*)d_in[14];
    const int* batch    = (const int*)d_in[15];
    const int* srcp = ei;
    const int* dstp = ei + EE;
    float* out = (float*)d_out;          // [NN*OUTD] h2, then [GG*OUTD] graph_emb
    float* out_emb = out + (size_t)NN * OUTD;

    k_zero_all<<<512, 256>>>();
    k_mean<<<256, 256>>>(ea);
    k_prep<<<1, 64>>>(We1, a_e1, We2, a_e2);

    // CSR build (graph shared by both layers)
    k_deg<<<(EE + 255) / 256, 256>>>(dstp);
    k_scan<<<1, 1024>>>();
    k_fill_self<<<(NN + 255) / 256, 256>>>();
    k_fill_edges<<<(EE + 255) / 256, 256>>>(srcp, dstp);

    k_edge_ae<<<(EE + 255) / 256, 256>>>(ea);

    // ---- layer 1 ----
    {
        dim3 g(F1 / 128, (NN + 127) / 128);
        k_sgemm<1><<<g, 256>>>(x, W1);
    }
    k_asad<1><<<(NN * NH * 32 + 255) / 256, 256>>>(a_src1, a_dst1);
    k_attn_agg<1><<<NN, F1 / 4>>>(b1, batch, nullptr);

    // ---- layer 2 ----
    {
        dim3 g(F2 / 128, (NN + 127) / 128);
        k_sgemm<2><<<g, 256>>>(nullptr, W2);
    }
    k_asad<2><<<(NN * NH * 32 + 255) / 256, 256>>>(a_src2, a_dst2);
    k_attn_agg<2><<<NN, F2 / 4>>>(b2, batch, out);

    // ---- pooling tail ----
    k_cnt<<<(NN + 255) / 256, 256>>>(batch);
    k_pool_div<<<(GG * OUTD + 255) / 256, 256>>>(out_emb);
}

// round 6
// speedup vs baseline: 2.1585x; 1.4148x over previous
#include <cuda_runtime.h>
#include <math.h>
#include <stdint.h>

#define NN   20000
#define EE   320000
#define ET   340000      // EE + NN self loops
#define GG   512
#define IND  74
#define KP1  80          // padded K for layer-1 A
#define EDD  12
#define HIDD 64
#define OUTD 128
#define NH   4
#define F1   256         // NH*HIDD
#define F2   512         // NH*OUTD
#define NEG  0.2f

// ---------------- scratch (static device globals; no allocation) ----------------
static __device__ __align__(16) float g_xpad[NN * KP1];   // x padded to K=80
static __device__ __align__(16) float g_h1pre[NN * F1];   // x @ W1
static __device__ __align__(16) float g_h1[NN * F1];      // layer-1 output
static __device__ __align__(16) float g_h2pre[NN * F2];   // h1 @ W2
static __device__ __align__(16) float g_as[NN * NH];
static __device__ __align__(16) float g_ad[NN * NH];
static __device__ __align__(16) float g_ae1[EE * NH];
static __device__ __align__(16) float g_ae2[EE * NH];
static __device__ float g_meanacc[EDD];
static __device__ float g_V1[EDD * NH];
static __device__ float g_V2[EDD * NH];
static __device__ float g_aeloop1[NH];
static __device__ float g_aeloop2[NH];
static __device__ float g_cnt[GG];
static __device__ float g_emb[GG * OUTD];
// CSR by destination
static __device__ int g_deg[NN];
static __device__ int g_off[NN + 1];
static __device__ int g_cur[NN];
static __device__ int g_csr_src[ET];
static __device__ int g_csr_eid[ET];   // -1 => self loop

// ---------------- helpers ----------------
__device__ __forceinline__ uint32_t f2tf(float f) {
    uint32_t u;
    asm("cvt.rna.tf32.f32 %0, %1;" : "=r"(u) : "f"(f));
    return u;
}
__device__ __forceinline__ void mma_tf32(float* c, const uint32_t* a, const uint32_t* b) {
    asm volatile(
        "mma.sync.aligned.m16n8k8.row.col.f32.tf32.tf32.f32 "
        "{%0,%1,%2,%3}, {%4,%5,%6,%7}, {%8,%9}, {%0,%1,%2,%3};"
        : "+f"(c[0]), "+f"(c[1]), "+f"(c[2]), "+f"(c[3])
        : "r"(a[0]), "r"(a[1]), "r"(a[2]), "r"(a[3]), "r"(b[0]), "r"(b[1]));
}

// ---------------- init ----------------
__global__ void k_zero_all() {
    int stride = gridDim.x * blockDim.x;
    int i = blockIdx.x * blockDim.x + threadIdx.x;
    for (int j = i; j < GG * OUTD; j += stride) g_emb[j] = 0.f;
    for (int j = i; j < NN; j += stride) g_deg[j] = 1;   // self loop
    if (i < GG) g_cnt[i] = 0.f;
    if (i < EDD) g_meanacc[i] = 0.f;
}

// ---------------- pad x into [NN, 80] ----------------
__global__ void k_pad_x(const float* __restrict__ x) {
    int i = blockIdx.x * blockDim.x + threadIdx.x;
    if (i >= NN * KP1) return;
    int n = i / KP1, k = i % KP1;
    g_xpad[i] = (k < IND) ? x[n * IND + k] : 0.f;
}

// ---------------- mean of edge_attr ----------------
__global__ void k_mean(const float* __restrict__ ea) {
    __shared__ float s[EDD];
    if (threadIdx.x < EDD) s[threadIdx.x] = 0.f;
    __syncthreads();
    float p[EDD];
#pragma unroll
    for (int d = 0; d < EDD; d++) p[d] = 0.f;
    for (int e = blockIdx.x * blockDim.x + threadIdx.x; e < EE; e += gridDim.x * blockDim.x) {
#pragma unroll
        for (int d = 0; d < EDD; d++) p[d] += ea[e * EDD + d];
    }
#pragma unroll
    for (int d = 0; d < EDD; d++) atomicAdd(&s[d], p[d]);
    __syncthreads();
    if (threadIdx.x < EDD) atomicAdd(&g_meanacc[threadIdx.x], s[threadIdx.x]);
}

// ---------------- tiny precompute: V matrices + self-loop attention terms ----------------
__global__ void k_prep(const float* __restrict__ We1, const float* __restrict__ aev1,
                       const float* __restrict__ We2, const float* __restrict__ aev2) {
    int t = threadIdx.x;  // 64 threads
    if (t < EDD * NH) {
        int d = t / NH, h = t % NH;
        float v1 = 0.f, v2 = 0.f;
        for (int c = 0; c < HIDD; c++) v1 += We1[d * F1 + h * HIDD + c] * aev1[h * HIDD + c];
        for (int c = 0; c < OUTD; c++) v2 += We2[d * F2 + h * OUTD + c] * aev2[h * OUTD + c];
        g_V1[t] = v1; g_V2[t] = v2;
    }
    __syncthreads();
    if (t < NH) {
        float s1 = 0.f, s2 = 0.f;
        for (int d = 0; d < EDD; d++) {
            float m = g_meanacc[d] * (1.f / (float)EE);
            s1 += m * g_V1[d * NH + t];
            s2 += m * g_V2[d * NH + t];
        }
        g_aeloop1[t] = s1; g_aeloop2[t] = s2;
    }
}

// ---------------- CSR build ----------------
__global__ void k_deg(const int* __restrict__ dst) {
    int e = blockIdx.x * blockDim.x + threadIdx.x;
    if (e < EE) atomicAdd(&g_deg[dst[e]], 1);
}
__global__ void k_scan() {   // single block, 1024 threads
    __shared__ int partial[1024];
    const int CHW = (NN + 1023) / 1024;
    int t = threadIdx.x;
    int base = t * CHW;
    int sum = 0;
    for (int i = 0; i < CHW; i++) {
        int idx = base + i;
        if (idx < NN) sum += g_deg[idx];
    }
    partial[t] = sum;
    __syncthreads();
    for (int ofs = 1; ofs < 1024; ofs <<= 1) {
        int v = 0;
        if (t >= ofs) v = partial[t - ofs];
        __syncthreads();
        if (t >= ofs) partial[t] += v;
        __syncthreads();
    }
    int run = (t == 0) ? 0 : partial[t - 1];
    for (int i = 0; i < CHW; i++) {
        int idx = base + i;
        if (idx < NN) { g_off[idx] = run; run += g_deg[idx]; }
    }
    if (t == 1023) g_off[NN] = partial[1023];
}
__global__ void k_fill_self() {
    int n = blockIdx.x * blockDim.x + threadIdx.x;
    if (n >= NN) return;
    int o = g_off[n];
    g_csr_src[o] = n;
    g_csr_eid[o] = -1;
    g_cur[n] = o + 1;
}
__global__ void k_fill_edges(const int* __restrict__ src, const int* __restrict__ dst) {
    int e = blockIdx.x * blockDim.x + threadIdx.x;
    if (e >= EE) return;
    int p = atomicAdd(&g_cur[dst[e]], 1);
    g_csr_src[p] = src[e];
    g_csr_eid[p] = e;
}

// ---------------- tf32 tensor-core GEMM: 128x128x16 tile, 8 warps of 32x64 ----------------
// LAYER==1: A=g_xpad [NN,80], B=W1 (KB=74 real rows), C=g_h1pre [NN,256]
// LAYER==2: A=g_h1  [NN,256], B=W2 (KB=256),          C=g_h2pre [NN,512]
template <int LAYER>
__global__ void __launch_bounds__(256) k_mm(const float* __restrict__ B) {
    constexpr int KP = (LAYER == 1) ? KP1 : F1;     // A row stride (mult of 16)
    constexpr int KB = (LAYER == 1) ? IND : F1;     // real K rows of B
    constexpr int NC = (LAYER == 1) ? F1  : F2;
    const float* __restrict__ A = (LAYER == 1) ? g_xpad : g_h1;
    float* __restrict__ C = (LAYER == 1) ? g_h1pre : g_h2pre;
    constexpr int BM = 128, BN = 128, BK = 16;
    constexpr int AS = 20;    // As row stride (pad)
    constexpr int BS = 132;   // Bs row stride (pad)

    __shared__ uint32_t As[2][BM * AS];
    __shared__ uint32_t Bs[2][BK * BS];

    int tid = threadIdx.x;
    int lane = tid & 31, warp = tid >> 5;
    int wm = (warp & 3) * 32;        // warp M offset
    int wn = (warp >> 2) * 64;       // warp N offset
    int row0 = blockIdx.y * BM, col0 = blockIdx.x * BN;

    float acc[2][8][4];
#pragma unroll
    for (int mt = 0; mt < 2; mt++)
#pragma unroll
        for (int nt = 0; nt < 8; nt++)
#pragma unroll
            for (int i = 0; i < 4; i++) acc[mt][nt][i] = 0.f;

    auto ldA = [&](int st, int k0) {
#pragma unroll
        for (int i = 0; i < 2; i++) {
            int idx = tid + i * 256;          // 0..511
            int m = idx >> 2, kq = (idx & 3) * 4;
            int gr = row0 + m;
            float4 v = make_float4(0.f, 0.f, 0.f, 0.f);
            if (gr < NN) v = *reinterpret_cast<const float4*>(&A[(size_t)gr * KP + k0 + kq]);
            uint32_t* p = &As[st][m * AS + kq];
            p[0] = f2tf(v.x); p[1] = f2tf(v.y); p[2] = f2tf(v.z); p[3] = f2tf(v.w);
        }
    };
    auto ldB = [&](int st, int k0) {
#pragma unroll
        for (int i = 0; i < 2; i++) {
            int idx = tid + i * 256;
            int k = idx >> 5, nq = (idx & 31) * 4;
            int gk = k0 + k;
            float4 v = make_float4(0.f, 0.f, 0.f, 0.f);
            if (gk < KB) v = *reinterpret_cast<const float4*>(&B[(size_t)gk * NC + col0 + nq]);
            uint32_t* p = &Bs[st][k * BS + nq];
            p[0] = f2tf(v.x); p[1] = f2tf(v.y); p[2] = f2tf(v.z); p[3] = f2tf(v.w);
        }
    };

    ldA(0, 0); ldB(0, 0);
    __syncthreads();
    constexpr int NK = KP / BK;
    for (int kt = 0; kt < NK; kt++) {
        int cur = kt & 1, nxt = cur ^ 1;
        if (kt + 1 < NK) { ldA(nxt, (kt + 1) * BK); ldB(nxt, (kt + 1) * BK); }
#pragma unroll
        for (int k8 = 0; k8 < 2; k8++) {
            uint32_t af[2][4];
#pragma unroll
            for (int mt = 0; mt < 2; mt++) {
                int r = wm + mt * 16 + (lane >> 2);
                int c = k8 * 8 + (lane & 3);
                af[mt][0] = As[cur][r * AS + c];
                af[mt][1] = As[cur][(r + 8) * AS + c];
                af[mt][2] = As[cur][r * AS + c + 4];
                af[mt][3] = As[cur][(r + 8) * AS + c + 4];
            }
            uint32_t bf[8][2];
#pragma unroll
            for (int nt = 0; nt < 8; nt++) {
                int c = wn + nt * 8 + (lane >> 2);
                int r = k8 * 8 + (lane & 3);
                bf[nt][0] = Bs[cur][r * BS + c];
                bf[nt][1] = Bs[cur][(r + 4) * BS + c];
            }
#pragma unroll
            for (int mt = 0; mt < 2; mt++)
#pragma unroll
                for (int nt = 0; nt < 8; nt++) mma_tf32(acc[mt][nt], af[mt], bf[nt]);
        }
        __syncthreads();
    }

#pragma unroll
    for (int mt = 0; mt < 2; mt++) {
        int r = row0 + wm + mt * 16 + (lane >> 2);
#pragma unroll
        for (int nt = 0; nt < 8; nt++) {
            int c = col0 + wn + nt * 8 + (lane & 3) * 2;
            if (r < NN)
                *reinterpret_cast<float2*>(&C[(size_t)r * NC + c]) =
                    make_float2(acc[mt][nt][0], acc[mt][nt][1]);
            if (r + 8 < NN)
                *reinterpret_cast<float2*>(&C[(size_t)(r + 8) * NC + c]) =
                    make_float2(acc[mt][nt][2], acc[mt][nt][3]);
        }
    }
}

// ---------------- per-node attention dots: as[n,h], ad[n,h] ----------------
template <int LAYER>
__global__ void k_asad(const float* __restrict__ a_s, const float* __restrict__ a_d) {
    constexpr int C = (LAYER == 1) ? HIDD : OUTD;
    const float* __restrict__ h = (LAYER == 1) ? g_h1pre : g_h2pre;
    int warp = (blockIdx.x * blockDim.x + threadIdx.x) >> 5;
    int lane = threadIdx.x & 31;
    if (warp >= NN * NH) return;
    int n = warp / NH, hh = warp % NH;
    const float* row = h + (size_t)n * (NH * C) + hh * C;
    const float* vs = a_s + hh * C;
    const float* vd = a_d + hh * C;
    float s = 0.f, d = 0.f;
    for (int c = lane; c < C; c += 32) {
        float v = row[c];
        s += v * vs[c];
        d += v * vd[c];
    }
#pragma unroll
    for (int o = 16; o; o >>= 1) {
        s += __shfl_down_sync(0xffffffffu, s, o);
        d += __shfl_down_sync(0xffffffffu, d, o);
    }
    if (lane == 0) { g_as[warp] = s; g_ad[warp] = d; }
}

// ---------------- per-edge attention terms (both layers in one pass) ----------------
__global__ void k_edge_ae(const float* __restrict__ ea) {
    int e = blockIdx.x * blockDim.x + threadIdx.x;
    if (e >= EE) return;
    float a1[NH] = {0.f, 0.f, 0.f, 0.f};
    float a2[NH] = {0.f, 0.f, 0.f, 0.f};
#pragma unroll
    for (int d = 0; d < EDD; d++) {
        float v = ea[e * EDD + d];
#pragma unroll
        for (int h = 0; h < NH; h++) {
            a1[h] += v * g_V1[d * NH + h];
            a2[h] += v * g_V2[d * NH + h];
        }
    }
#pragma unroll
    for (int h = 0; h < NH; h++) {
        g_ae1[e * NH + h] = a1[h];
        g_ae2[e * NH + h] = a2[h];
    }
}

// ---------------- fused attention: online softmax + aggregate (one block per dst) ----------------
template <int LAYER>
__global__ void k_attn_agg(const float* __restrict__ bias, const int* __restrict__ batch,
                           float* __restrict__ out) {
    constexpr int F  = (LAYER == 1) ? F1 : F2;
    constexpr int CH = F / NH;
    constexpr int T  = F / 4;            // threads per block
    const float* __restrict__ ae = (LAYER == 1) ? g_ae1 : g_ae2;
    const float* __restrict__ aeloop = (LAYER == 1) ? g_aeloop1 : g_aeloop2;
    const float4* __restrict__ hp =
        reinterpret_cast<const float4*>((LAYER == 1) ? g_h1pre : g_h2pre);

    int n = blockIdx.x;
    int t = threadIdx.x;
    int h = (t * 4) / CH;
    int begin = g_off[n], end = g_off[n + 1];
    float ad_n = g_ad[n * NH + h];
    float av_loop = aeloop[h];

    float mx = -INFINITY, ssum = 0.f;
    float4 acc = make_float4(0.f, 0.f, 0.f, 0.f);
    for (int i = begin; i < end; i++) {
        int s = __ldg(&g_csr_src[i]);
        int eid = __ldg(&g_csr_eid[i]);
        float av = (eid >= 0) ? __ldg(&ae[eid * NH + h]) : av_loop;
        float a = __ldg(&g_as[s * NH + h]) + ad_n + av;
        a = (a >= 0.f) ? a : NEG * a;
        if (a > mx) {
            float sc = __expf(mx - a);
            ssum *= sc; acc.x *= sc; acc.y *= sc; acc.z *= sc; acc.w *= sc;
            mx = a;
        }
        float ex = __expf(a - mx);
        ssum += ex;
        float4 v = hp[(size_t)s * T + t];
        acc.x += ex * v.x; acc.y += ex * v.y; acc.z += ex * v.z; acc.w += ex * v.w;
    }
    float inv = 1.f / (ssum + 1e-16f);
    acc.x *= inv; acc.y *= inv; acc.z *= inv; acc.w *= inv;

    if (LAYER == 1) {
        float4 b = *reinterpret_cast<const float4*>(&bias[t * 4]);
        float4 r;
        r.x = fmaxf(acc.x + b.x, 0.f);
        r.y = fmaxf(acc.y + b.y, 0.f);
        r.z = fmaxf(acc.z + b.z, 0.f);
        r.w = fmaxf(acc.w + b.w, 0.f);
        reinterpret_cast<float4*>(g_h1)[(size_t)n * T + t] = r;
    } else {
        __shared__ float sbuf[F2];
        *reinterpret_cast<float4*>(&sbuf[t * 4]) = acc;
        __syncthreads();
        int c = t;   // T == 128 == OUTD
        float v = 0.25f * (sbuf[c] + sbuf[OUTD + c] + sbuf[2 * OUTD + c] + sbuf[3 * OUTD + c])
                  + bias[c];
        v = fmaxf(v, 0.f);
        out[(size_t)n * OUTD + c] = v;
        atomicAdd(&g_emb[batch[n] * OUTD + c], v);
    }
}

// ---------------- pooling tail ----------------
__global__ void k_cnt(const int* __restrict__ batch) {
    int n = blockIdx.x * blockDim.x + threadIdx.x;
    if (n < NN) atomicAdd(&g_cnt[batch[n]], 1.f);
}
__global__ void k_pool_div(float* __restrict__ out_emb) {
    int i = blockIdx.x * blockDim.x + threadIdx.x;
    if (i >= GG * OUTD) return;
    int g = i / OUTD;
    out_emb[i] = g_emb[i] / fmaxf(g_cnt[g], 1.f);
}

// ---------------- launcher ----------------
extern "C" void kernel_launch(void* const* d_in, const int* in_sizes, int n_in,
                              void* d_out, int out_size) {
    const float* x      = (const float*)d_in[0];
    const float* ea     = (const float*)d_in[1];
    const float* W1     = (const float*)d_in[2];
    const float* a_src1 = (const float*)d_in[3];
    const float* a_dst1 = (const float*)d_in[4];
    const float* We1    = (const float*)d_in[5];
    const float* a_e1   = (const float*)d_in[6];
    const float* b1     = (const float*)d_in[7];
    const float* W2     = (const float*)d_in[8];
    const float* a_src2 = (const float*)d_in[9];
    const float* a_dst2 = (const float*)d_in[10];
    const float* We2    = (const float*)d_in[11];
    const float* a_e2   = (const float*)d_in[12];
    const float* b2     = (const float*)d_in[13];
    const int* ei       = (const int*)d_in[14];
    const int* batch    = (const int*)d_in[15];
    const int* srcp = ei;
    const int* dstp = ei + EE;
    float* out = (float*)d_out;          // [NN*OUTD] h2, then [GG*OUTD] graph_emb
    float* out_emb = out + (size_t)NN * OUTD;

    k_zero_all<<<512, 256>>>();
    k_pad_x<<<(NN * KP1 + 255) / 256, 256>>>(x);
    k_mean<<<256, 256>>>(ea);
    k_prep<<<1, 64>>>(We1, a_e1, We2, a_e2);

    // CSR build (graph shared by both layers)
    k_deg<<<(EE + 255) / 256, 256>>>(dstp);
    k_scan<<<1, 1024>>>();
    k_fill_self<<<(NN + 255) / 256, 256>>>();
    k_fill_edges<<<(EE + 255) / 256, 256>>>(srcp, dstp);

    k_edge_ae<<<(EE + 255) / 256, 256>>>(ea);

    // ---- layer 1 ----
    {
        dim3 g(F1 / 128, (NN + 127) / 128);
        k_mm<1><<<g, 256>>>(W1);
    }
    k_asad<1><<<(NN * NH * 32 + 255) / 256, 256>>>(a_src1, a_dst1);
    k_attn_agg<1><<<NN, F1 / 4>>>(b1, batch, nullptr);

    // ---- layer 2 ----
    {
        dim3 g(F2 / 128, (NN + 127) / 128);
        k_mm<2><<<g, 256>>>(W2);
    }
    k_asad<2><<<(NN * NH * 32 + 255) / 256, 256>>>(a_src2, a_dst2);
    k_attn_agg<2><<<NN, F2 / 4>>>(b2, batch, out);

    // ---- pooling tail ----
    k_cnt<<<(NN + 255) / 256, 256>>>(batch);
    k_pool_div<<<(GG * OUTD + 255) / 256, 256>>>(out_emb);
}